// round 2
// baseline (speedup 1.0000x reference)
#include <cuda_runtime.h>
#include <cstdint>

#define B_ 256
#define T_ 1024
#define D_ 64
#define H_ 100
#define G_ 400   // 4*H
#define L2E 1.44269504088896f

// Scratch: precomputed input-gate contributions, PERMUTED row order:
// xg[b][t][tid] holds gate-row ((tid&3)*H + (tid>>2)).  ~419 MB.
__device__ float g_xg[(size_t)B_ * T_ * G_];

// ---------------------------------------------------------------------------
// Packed f32x2 helpers (Blackwell packed FP32 pipe: 2 MACs per issue)
// ---------------------------------------------------------------------------
__device__ __forceinline__ unsigned long long ffma2(unsigned long long a,
                                                    unsigned long long b,
                                                    unsigned long long c) {
    unsigned long long d;
    asm("fma.rn.f32x2 %0, %1, %2, %3;" : "=l"(d) : "l"(a), "l"(b), "l"(c));
    return d;
}
__device__ __forceinline__ unsigned long long add2(unsigned long long a,
                                                   unsigned long long b) {
    unsigned long long d;
    asm("add.rn.f32x2 %0, %1, %2;" : "=l"(d) : "l"(a), "l"(b));
    return d;
}
__device__ __forceinline__ unsigned long long pack2(float x, float y) {
    return ((unsigned long long)__float_as_uint(y) << 32) |
           (unsigned long long)__float_as_uint(x);
}
__device__ __forceinline__ float lo2(unsigned long long v) {
    return __uint_as_float((unsigned)v);
}
__device__ __forceinline__ float hi2(unsigned long long v) {
    return __uint_as_float((unsigned)(v >> 32));
}
__device__ __forceinline__ float ex2a(float x) {
    float r; asm("ex2.approx.ftz.f32 %0, %1;" : "=f"(r) : "f"(x)); return r;
}
__device__ __forceinline__ float rcpa(float x) {
    float r; asm("rcp.approx.ftz.f32 %0, %1;" : "=f"(r) : "f"(x)); return r;
}
// Uniform activation: sigmoid(x) = 1 - 1/(e^x + 1)   (lm = log2e,  s = 1)
//                     tanh(x)    = 1 - 2/(e^2x + 1)  (lm = 2log2e, s = 2)
__device__ __forceinline__ float uact(float x, float lm, float s) {
    return 1.0f - s * rcpa(ex2a(lm * x) + 1.0f);
}

// ---------------------------------------------------------------------------
// Kernel 1: xg[b,t,tid] = x[b,t,:] . W_ih[row,:] + (b_ih+b_hh)[row],
//           row = (tid&3)*H + (tid>>2)  (quad-permuted for the lstm kernel).
// Grid (T/64, B), 512 threads. 4-timestep inner tile -> 8 indep FFMA2 chains.
// ---------------------------------------------------------------------------
__global__ __launch_bounds__(512, 1)
void xg_kernel(const float* __restrict__ x,
               const float* __restrict__ W_ih,
               const float* __restrict__ b_ih,
               const float* __restrict__ b_hh) {
    __shared__ ulonglong2 xs[64][16];   // 64 t x 64 k fp32 tile (16 KB)

    const int b   = blockIdx.y;
    const int t0  = blockIdx.x * 64;
    const int tid = threadIdx.x;

    {   // coalesced float4 tile load
        const float4* src = (const float4*)(x + ((size_t)b * T_ + t0) * D_);
        float4* dst = (float4*)xs;
        for (int i = tid; i < 64 * 16; i += 512) dst[i] = src[i];
    }

    unsigned long long w2[32];
    float bias = 0.0f;
    if (tid < G_) {
        const int row = (tid & 3) * H_ + (tid >> 2);
        const float4* wrow = (const float4*)(W_ih + (size_t)row * D_);
#pragma unroll
        for (int i = 0; i < 16; i++) {
            float4 v = wrow[i];
            w2[2 * i]     = pack2(v.x, v.y);
            w2[2 * i + 1] = pack2(v.z, v.w);
        }
        bias = b_ih[row] + b_hh[row];
    }
    __syncthreads();

    if (tid < G_) {
        float* out = g_xg + ((size_t)b * T_ + t0) * G_ + tid;
        for (int t = 0; t < 64; t += 4) {
            unsigned long long a[8] = {0, 0, 0, 0, 0, 0, 0, 0};
#pragma unroll
            for (int i = 0; i < 16; i++) {
                ulonglong2 x0 = xs[t + 0][i];
                ulonglong2 x1 = xs[t + 1][i];
                ulonglong2 x2 = xs[t + 2][i];
                ulonglong2 x3 = xs[t + 3][i];
                a[0] = ffma2(w2[2 * i],     x0.x, a[0]);
                a[1] = ffma2(w2[2 * i + 1], x0.y, a[1]);
                a[2] = ffma2(w2[2 * i],     x1.x, a[2]);
                a[3] = ffma2(w2[2 * i + 1], x1.y, a[3]);
                a[4] = ffma2(w2[2 * i],     x2.x, a[4]);
                a[5] = ffma2(w2[2 * i + 1], x2.y, a[5]);
                a[6] = ffma2(w2[2 * i],     x3.x, a[6]);
                a[7] = ffma2(w2[2 * i + 1], x3.y, a[7]);
            }
#pragma unroll
            for (int q = 0; q < 4; q++) {
                unsigned long long s2 = add2(a[2 * q], a[2 * q + 1]);
                out[(size_t)(t + q) * G_] = lo2(s2) + hi2(s2) + bias;
            }
        }
    }
}

// ---------------------------------------------------------------------------
// Kernel 2: recurrence, quad-gate layout.
// 128 blocks x 2 batch rows. Thread: gate = tid&3, j = tid>>2; owns W_hh row
// (gate*H + j) in 50 packed f32x2 regs. Per step: matvec for both batches,
// uniform activation, quad shfl gather of {i,f,g,o}, redundant c-update in
// registers, gate0 lane stores h. ONE barrier per step, double-buffered h.
// ---------------------------------------------------------------------------
__global__ __launch_bounds__(416, 1)
void lstm_kernel(const float* __restrict__ h0,
                 const float* __restrict__ c0,
                 const float* __restrict__ W_hh,
                 const float* __restrict__ W_fc,
                 const float* __restrict__ b_fc,
                 float* __restrict__ out) {
    __shared__ ulonglong2 hs[2][2][25];  // [buf][batch][100 floats]
    __shared__ float wfc_s[H_];

    const int tid    = threadIdx.x;
    const int batch0 = blockIdx.x * 2;
    const int gate   = tid & 3;
    const int j      = tid >> 2;
    const int lane   = tid & 31;
    const unsigned qmask = 0xFu << (lane & 28);
    const int qbase  = lane & 28;

    // init h buffer 0 from h0
    if (tid < 2 * H_) {
        const int b = tid / H_, jj = tid - b * H_;
        ((float*)hs[0][b])[jj] = h0[(size_t)(batch0 + b) * H_ + jj];
    }
    if (tid < H_) wfc_s[tid] = W_fc[tid];

    unsigned long long w2[50];
    float cr0 = 0.0f, cr1 = 0.0f;   // cell state (redundant across quad lanes)
    float lm = L2E, sc = 1.0f;
    const float* xp0 = g_xg + (size_t)(batch0)     * T_ * G_ + tid;
    const float* xp1 = g_xg + (size_t)(batch0 + 1) * T_ * G_ + tid;
    float xgc0 = 0.0f, xgc1 = 0.0f;

    if (tid < G_) {
        const int row = gate * H_ + j;
        const float4* wrow = (const float4*)(W_hh + (size_t)row * H_);
#pragma unroll
        for (int i = 0; i < 25; i++) {
            float4 v = wrow[i];
            w2[2 * i]     = pack2(v.x, v.y);
            w2[2 * i + 1] = pack2(v.z, v.w);
        }
        cr0 = c0[(size_t)(batch0)     * H_ + j];
        cr1 = c0[(size_t)(batch0 + 1) * H_ + j];
        if (gate == 2) { lm = 2.0f * L2E; sc = 2.0f; }
        xgc0 = xp0[0];
        xgc1 = xp1[0];
    }
    __syncthreads();

    int cur = 0;
    for (int t = 0; t < T_; t++) {
        float xgn0 = 0.0f, xgn1 = 0.0f;
        if (tid < G_ && t + 1 < T_) {          // prefetch next step's xg
            xgn0 = xp0[(size_t)(t + 1) * G_];
            xgn1 = xp1[(size_t)(t + 1) * G_];
        }

        if (tid < G_) {
            unsigned long long a0 = 0, a1 = 0, b0 = 0, b1 = 0;
#pragma unroll
            for (int i = 0; i < 25; i++) {
                ulonglong2 hv = hs[cur][0][i];   // broadcast LDS.128
                a0 = ffma2(w2[2 * i],     hv.x, a0);
                a1 = ffma2(w2[2 * i + 1], hv.y, a1);
            }
#pragma unroll
            for (int i = 0; i < 25; i++) {
                ulonglong2 hv = hs[cur][1][i];
                b0 = ffma2(w2[2 * i],     hv.x, b0);
                b1 = ffma2(w2[2 * i + 1], hv.y, b1);
            }
            unsigned long long s0 = add2(a0, a1);
            unsigned long long s1 = add2(b0, b1);
            float acc0 = lo2(s0) + hi2(s0) + xgc0;
            float acc1 = lo2(s1) + hi2(s1) + xgc1;

            // uniform activation (no divergence)
            float r0 = uact(acc0, lm, sc);
            float r1 = uact(acc1, lm, sc);

            // quad gather of {i,f,g,o} for both batches
            float i0 = __shfl_sync(qmask, r0, qbase + 0);
            float f0 = __shfl_sync(qmask, r0, qbase + 1);
            float g0 = __shfl_sync(qmask, r0, qbase + 2);
            float o0 = __shfl_sync(qmask, r0, qbase + 3);
            float i1 = __shfl_sync(qmask, r1, qbase + 0);
            float f1 = __shfl_sync(qmask, r1, qbase + 1);
            float g1 = __shfl_sync(qmask, r1, qbase + 2);
            float o1 = __shfl_sync(qmask, r1, qbase + 3);

            // redundant (consistent) c update in all 4 quad lanes
            cr0 = f0 * cr0 + i0 * g0;
            cr1 = f1 * cr1 + i1 * g1;
            float h0v = o0 * uact(cr0, 2.0f * L2E, 2.0f);
            float h1v = o1 * uact(cr1, 2.0f * L2E, 2.0f);

            if (gate == 0) {
                ((float*)hs[cur ^ 1][0])[j] = h0v;
                ((float*)hs[cur ^ 1][1])[j] = h1v;
            }
            xgc0 = xgn0;
            xgc1 = xgn1;
        }
        __syncthreads();
        cur ^= 1;
    }

    // T even -> final h is in hs[cur] (== hs[0]); protected by last barrier.
    if (tid < 2) {
        float acc = b_fc[0];
        const float* hp = (const float*)hs[cur][tid];
#pragma unroll 4
        for (int jj = 0; jj < H_; jj++) acc += hp[jj] * wfc_s[jj];
        out[batch0 + tid] = acc;
    }
}

// ---------------------------------------------------------------------------
extern "C" void kernel_launch(void* const* d_in, const int* in_sizes, int n_in,
                              void* d_out, int out_size) {
    const float* x    = (const float*)d_in[0];
    const float* h0   = (const float*)d_in[1];
    const float* c0   = (const float*)d_in[2];
    const float* W_ih = (const float*)d_in[3];
    const float* W_hh = (const float*)d_in[4];
    const float* b_ih = (const float*)d_in[5];
    const float* b_hh = (const float*)d_in[6];
    const float* W_fc = (const float*)d_in[7];
    const float* b_fc = (const float*)d_in[8];
    float* out = (float*)d_out;

    dim3 grid1(T_ / 64, B_);
    xg_kernel<<<grid1, 512>>>(x, W_ih, b_ih, b_hh);

    lstm_kernel<<<B_ / 2, 416>>>(h0, c0, W_hh, W_fc, b_fc, out);
}